// round 14
// baseline (speedup 1.0000x reference)
#include <cuda_runtime.h>
#include <cuda_bf16.h>
#include <cstdint>

// Problem constants
#define BB   4
#define SS   2048
#define DD   1024
#define HH   16
#define DKH  64
#define MM   (BB*SS)   // 8192 rows

// bf16 hi/lo scratch for Q,K,V ; fp32 context (K-permuted); tf32-rounded
// K-permuted copies of x, W. Permutation within each 16-k block:
//   j = 4*(k%4) + k/4
__device__ __align__(16) __nv_bfloat16 g_qh[(size_t)MM*DD];
__device__ __align__(16) __nv_bfloat16 g_ql[(size_t)MM*DD];
__device__ __align__(16) __nv_bfloat16 g_kh[(size_t)MM*DD];
__device__ __align__(16) __nv_bfloat16 g_kl[(size_t)MM*DD];
__device__ __align__(16) __nv_bfloat16 g_vh[(size_t)MM*DD];
__device__ __align__(16) __nv_bfloat16 g_vl[(size_t)MM*DD];
__device__ __align__(16) float g_C[(size_t)MM*DD];
__device__ __align__(16) float g_xr[(size_t)MM*DD];
__device__ __align__(16) float g_wr[4][(size_t)DD*DD];

// ---------------------------------------------------------------------------
// helpers
// ---------------------------------------------------------------------------
__device__ __forceinline__ float f2tf32f(float f) {
    unsigned u;
    asm("cvt.rna.tf32.f32 %0, %1;" : "=r"(u) : "f"(f));
    return __uint_as_float(u);
}
__device__ __forceinline__ void mma_tf32(float c[4], unsigned a0, unsigned a1,
                                         unsigned a2, unsigned a3,
                                         unsigned b0, unsigned b1) {
    asm volatile(
        "mma.sync.aligned.m16n8k8.row.col.f32.tf32.tf32.f32 "
        "{%0,%1,%2,%3}, {%4,%5,%6,%7}, {%8,%9}, {%0,%1,%2,%3};\n"
        : "+f"(c[0]), "+f"(c[1]), "+f"(c[2]), "+f"(c[3])
        : "r"(a0), "r"(a1), "r"(a2), "r"(a3), "r"(b0), "r"(b1));
}
__device__ __forceinline__ void mma_bf16(float c[4], const uint32_t a[4],
                                         uint32_t b0, uint32_t b1) {
    asm volatile(
        "mma.sync.aligned.m16n8k16.row.col.f32.bf16.bf16.f32 "
        "{%0,%1,%2,%3}, {%4,%5,%6,%7}, {%8,%9}, {%0,%1,%2,%3};\n"
        : "+f"(c[0]), "+f"(c[1]), "+f"(c[2]), "+f"(c[3])
        : "r"(a[0]), "r"(a[1]), "r"(a[2]), "r"(a[3]), "r"(b0), "r"(b1));
}
__device__ __forceinline__ uint32_t pkbf(float x, float y) {
    __nv_bfloat162 t = __floats2bfloat162_rn(x, y);
    return *reinterpret_cast<uint32_t*>(&t);
}
__device__ __forceinline__ void split2(float x, float y, uint32_t& hi, uint32_t& lo) {
    __nv_bfloat16 hx = __float2bfloat16(x), hy = __float2bfloat16(y);
    hi = (uint32_t)__bfloat16_as_ushort(hx) | ((uint32_t)__bfloat16_as_ushort(hy) << 16);
    lo = pkbf(x - __bfloat162float(hx), y - __bfloat162float(hy));
}
__device__ __forceinline__ uint32_t smem_u32(const void* p) {
    uint32_t a;
    asm("{ .reg .u64 t; cvta.to.shared.u64 t, %1; cvt.u32.u64 %0, t; }" : "=r"(a) : "l"(p));
    return a;
}
__device__ __forceinline__ void ldsm_x4(uint32_t r[4], uint32_t addr) {
    asm volatile("ldmatrix.sync.aligned.m8n8.x4.shared.b16 {%0,%1,%2,%3}, [%4];"
                 : "=r"(r[0]), "=r"(r[1]), "=r"(r[2]), "=r"(r[3]) : "r"(addr));
}
__device__ __forceinline__ void ldsm_x4_t(uint32_t r[4], uint32_t addr) {
    asm volatile("ldmatrix.sync.aligned.m8n8.x4.trans.shared.b16 {%0,%1,%2,%3}, [%4];"
                 : "=r"(r[0]), "=r"(r[1]), "=r"(r[2]), "=r"(r[3]) : "r"(addr));
}
__device__ __forceinline__ void cpa16(uint32_t dst, const void* src) {
    asm volatile("cp.async.cg.shared.global [%0], [%1], 16;" :: "r"(dst), "l"(src));
}

// ---------------------------------------------------------------------------
// Fused fp32 -> tf32-rounded, K-permuted pre-pass for x + 4 weights (1 launch)
// ---------------------------------------------------------------------------
#define NX4 (MM*DD/4)
#define NW4 (DD*DD/4)

__global__ void cvt_all(const float* __restrict__ x,
                        const float* __restrict__ wq, const float* __restrict__ wk,
                        const float* __restrict__ wv, const float* __restrict__ wo,
                        float* __restrict__ xr, float* __restrict__ wr)
{
    int i = blockIdx.x * blockDim.x + threadIdx.x;
    const float* src;
    float* dst;
    size_t li;
    if (i < NX4) {
        src = x; dst = xr; li = (size_t)i * 4;
    } else {
        int j = i - NX4;
        if (j >= 4 * NW4) return;
        const int wsel = j >> 18;             // NW4 = 2^18
        const int r    = j & (NW4 - 1);
        src = (wsel == 0) ? wq : (wsel == 1) ? wk : (wsel == 2) ? wv : wo;
        dst = wr + (size_t)wsel * DD * DD;
        li  = (size_t)r * 4;
    }
    float4 v = *(const float4*)&src[li];
    const int k0 = (int)(li & (DD - 1));
    const int c  = (k0 & 15) >> 2;
    float* d = dst + (li - (k0 & 15)) + c;
    d[0]  = f2tf32f(v.x);
    d[4]  = f2tf32f(v.y);
    d[8]  = f2tf32f(v.z);
    d[12] = f2tf32f(v.w);
}

// ---------------------------------------------------------------------------
// TF32 tensor-core GEMM (NT), cp.async 6-stage pipeline, ONE barrier per
// 2 k16-tiles, K-permuted operands. MODE 0: single W fp32 out. MODE 1: QKV.
// ---------------------------------------------------------------------------
#define BM   128
#define BN   128
#define BKG  16
#define NSTG 6
#define ASTGF (BM*16)
#define BSTGF (BN*16)
#define GSMEMB (NSTG*(ASTGF+BSTGF)*4)   // 98304

#define U(x) __float_as_uint(x)

template<int MODE>
__global__ __launch_bounds__(256, 2)
void gemm_tf32(const float* __restrict__ A, const float* __restrict__ Wbase,
               float* __restrict__ C,
               __nv_bfloat16* __restrict__ Qh, __nv_bfloat16* __restrict__ Ql,
               __nv_bfloat16* __restrict__ Kh, __nv_bfloat16* __restrict__ Kl,
               __nv_bfloat16* __restrict__ Vh, __nv_bfloat16* __restrict__ Vl,
               int M, int N, int K)
{
    extern __shared__ __align__(16) float smf[];
    float (*As)[BM][16] = (float (*)[BM][16])smf;
    float (*Bs)[BN][16] = (float (*)[BN][16])(smf + NSTG * ASTGF);

    const int t    = threadIdx.x;
    const int lane = t & 31;
    const int wid  = t >> 5;
    const int wm   = (wid & 1) * 64;
    const int wn   = (wid >> 1) * 32;
    const int row0 = blockIdx.y * BM;

    int col0;
    const float* W;
    __nv_bfloat16 *Xh = nullptr, *Xl = nullptr;
    if (MODE == 1) {
        const int mat = blockIdx.x >> 3;
        col0 = (blockIdx.x & 7) * BN;
        W    = Wbase + (size_t)mat * DD * DD;
        Xh   = (mat == 0) ? Qh : (mat == 1) ? Kh : Vh;
        Xl   = (mat == 0) ? Ql : (mat == 1) ? Kl : Vl;
    } else {
        col0 = blockIdx.x * BN;
        W    = Wbase;
    }

    const int lm  = t >> 2;
    const int lkv = (t & 3) << 2;

    const float* Arow0 = &A[(size_t)(row0 + lm) * K + lkv];
    const float* Arow1 = &A[(size_t)(row0 + lm + 64) * K + lkv];
    const float* Wrow0 = &W[(size_t)(col0 + lm) * K + lkv];
    const float* Wrow1 = &W[(size_t)(col0 + lm + 64) * K + lkv];

    const uint32_t sA0 = smem_u32(&As[0][lm][lkv]);
    const uint32_t sA1 = smem_u32(&As[0][lm + 64][lkv]);
    const uint32_t sB0 = smem_u32(&Bs[0][lm][lkv]);
    const uint32_t sB1 = smem_u32(&Bs[0][lm + 64][lkv]);

    float acc[4][4][4];
#pragma unroll
    for (int i = 0; i < 4; i++)
#pragma unroll
        for (int j = 0; j < 4; j++)
#pragma unroll
            for (int r = 0; r < 4; r++) acc[i][j][r] = 0.0f;

    const int lq = lane & 3;
    const int lg = lane >> 2;
    const int pairs = K / (2 * BKG);   // 32

    // prologue: two groups of two tiles each (stages 0,1 and 2,3)
#pragma unroll
    for (int gidx = 0; gidx < 2; gidx++) {
#pragma unroll
        for (int u = 0; u < 2; u++) {
            const int st = gidx * 2 + u;
            const int k0 = st * BKG;
            const uint32_t ao = st * (ASTGF * 4), bo = st * (BSTGF * 4);
            cpa16(sA0 + ao, Arow0 + k0);
            cpa16(sA1 + ao, Arow1 + k0);
            cpa16(sB0 + bo, Wrow0 + k0);
            cpa16(sB1 + bo, Wrow1 + k0);
        }
        asm volatile("cp.async.commit_group;");
    }

    int st_w = 4;   // next pair of stages to write
    int st_r = 0;   // next pair of stages to read
    for (int ip = 0; ip < pairs; ip++) {
        asm volatile("cp.async.wait_group 1;");
        __syncthreads();   // protects reuse of stages st_w, st_w+1

        if (2 * ip + 4 < 2 * pairs) {
#pragma unroll
            for (int u = 0; u < 2; u++) {
                const int st = st_w + u;
                const int k0 = (2 * ip + 4 + u) * BKG;
                const uint32_t ao = st * (ASTGF * 4), bo = st * (BSTGF * 4);
                cpa16(sA0 + ao, Arow0 + k0);
                cpa16(sA1 + ao, Arow1 + k0);
                cpa16(sB0 + bo, Wrow0 + k0);
                cpa16(sB1 + bo, Wrow1 + k0);
            }
        }
        asm volatile("cp.async.commit_group;");
        st_w += 2; if (st_w == NSTG) st_w = 0;

#pragma unroll
        for (int u = 0; u < 2; u++) {
            const int s = st_r + u;
            float4 fb[4];
#pragma unroll
            for (int ni = 0; ni < 4; ni++)
                fb[ni] = *(const float4*)&Bs[s][wn + ni * 8 + lg][4 * lq];
#pragma unroll
            for (int mi = 0; mi < 4; mi++) {
                const int mb = wm + mi * 16 + lg;
                const float4 lo = *(const float4*)&As[s][mb][4 * lq];
                const float4 hi = *(const float4*)&As[s][mb + 8][4 * lq];
#pragma unroll
                for (int ni = 0; ni < 4; ni++) {
                    mma_tf32(acc[mi][ni], U(lo.x), U(hi.x), U(lo.y), U(hi.y),
                             U(fb[ni].x), U(fb[ni].y));
                    mma_tf32(acc[mi][ni], U(lo.z), U(hi.z), U(lo.w), U(hi.w),
                             U(fb[ni].z), U(fb[ni].w));
                }
            }
        }
        st_r += 2; if (st_r == NSTG) st_r = 0;
    }

#pragma unroll
    for (int mi = 0; mi < 4; mi++) {
        const int r0 = row0 + wm + mi * 16 + lg;
#pragma unroll
        for (int ni = 0; ni < 4; ni++) {
            const int c0 = col0 + wn + ni * 8 + lq * 2;
            if (MODE == 1) {
                uint32_t h0, l0, h1, l1;
                split2(acc[mi][ni][0], acc[mi][ni][1], h0, l0);
                split2(acc[mi][ni][2], acc[mi][ni][3], h1, l1);
                *(uint32_t*)&Xh[(size_t)r0 * DD + c0]       = h0;
                *(uint32_t*)&Xl[(size_t)r0 * DD + c0]       = l0;
                *(uint32_t*)&Xh[(size_t)(r0 + 8) * DD + c0] = h1;
                *(uint32_t*)&Xl[(size_t)(r0 + 8) * DD + c0] = l1;
            } else {
                *(float2*)&C[(size_t)r0 * N + c0]       = make_float2(acc[mi][ni][0], acc[mi][ni][1]);
                *(float2*)&C[(size_t)(r0 + 8) * N + c0] = make_float2(acc[mi][ni][2], acc[mi][ni][3]);
            }
        }
    }
}

// ---------------------------------------------------------------------------
// Causal flash attention — round-12 body (frozen), K-permuted CTX epilogue.
// ---------------------------------------------------------------------------
#define KP   72
#define TSH  (64*KP)
#define RB   144
#define TSB  (64*RB)

__global__ __launch_bounds__(128, 3)
void attn_mma(const __nv_bfloat16* __restrict__ Qhg, const __nv_bfloat16* __restrict__ Qlg,
              const __nv_bfloat16* __restrict__ Khg, const __nv_bfloat16* __restrict__ Klg,
              const __nv_bfloat16* __restrict__ Vhg, const __nv_bfloat16* __restrict__ Vlg,
              float* __restrict__ CTX)
{
    __shared__ __align__(16) unsigned short sm[4 * TSH];

    const int tid  = threadIdx.x;
    const int lane = tid & 31;
    const int w    = tid >> 5;
    const int g    = lane >> 2;
    const int t4   = lane & 3;
    const int qt   = (int)gridDim.x - 1 - (int)blockIdx.x;
    const int h    = blockIdx.y;
    const int b    = blockIdx.z;
    const int r_lo = qt * 64 + w * 16 + g;
    const int r_hi = r_lo + 8;
    const int hoff = h * DKH;

    const uint32_t sb  = smem_u32(sm);
    const uint32_t Kh0 = sb, Kl0 = sb + TSB, Vh0 = sb + 2 * TSB, Vl0 = sb + 3 * TSB;
    const uint32_t lkK = (uint32_t)((lane & 7) * RB + (lane >> 3) * 16);
    const uint32_t lkV = (uint32_t)(lane * RB);

    uint32_t qh[4][4], ql[4][4];
#pragma unroll
    for (int c = 0; c < 4; c++) {
        const size_t plo = (size_t)(b * SS + r_lo) * DD + hoff + c * 16 + 2 * t4;
        const size_t phi = (size_t)(b * SS + r_hi) * DD + hoff + c * 16 + 2 * t4;
        qh[c][0] = *(const uint32_t*)&Qhg[plo];
        qh[c][1] = *(const uint32_t*)&Qhg[phi];
        qh[c][2] = *(const uint32_t*)&Qhg[plo + 8];
        qh[c][3] = *(const uint32_t*)&Qhg[phi + 8];
        ql[c][0] = *(const uint32_t*)&Qlg[plo];
        ql[c][1] = *(const uint32_t*)&Qlg[phi];
        ql[c][2] = *(const uint32_t*)&Qlg[plo + 8];
        ql[c][3] = *(const uint32_t*)&Qlg[phi + 8];
    }

    float o[8][4];
#pragma unroll
    for (int j = 0; j < 8; j++)
#pragma unroll
        for (int e = 0; e < 4; e++) o[j][e] = 0.0f;
    float m_lo = -1e30f, m_hi = -1e30f;
    float l_lo = 0.0f,  l_hi = 0.0f;

    for (int kt = 0; kt <= qt; kt++) {
        const int k0 = kt * 64;
        __syncthreads();
        {
            const size_t gbase = (size_t)(b * SS + k0) * DD + hoff;
#pragma unroll
            for (int i = 0; i < 4; i++) {
                int idx = tid + i * 128;
                int r   = idx >> 3;
                int c8  = (idx & 7) << 3;
                size_t go = gbase + (size_t)r * DD + c8;
                int so = r * KP + c8;
                *(uint4*)&sm[0 * TSH + so] = *(const uint4*)&Khg[go];
                *(uint4*)&sm[1 * TSH + so] = *(const uint4*)&Klg[go];
                *(uint4*)&sm[2 * TSH + so] = *(const uint4*)&Vhg[go];
                *(uint4*)&sm[3 * TSH + so] = *(const uint4*)&Vlg[go];
            }
        }
        __syncthreads();

        float s[8][4];
#pragma unroll
        for (int j = 0; j < 8; j++) {
            s[j][0] = s[j][1] = s[j][2] = s[j][3] = 0.0f;
            const uint32_t aKh = Kh0 + j * (8 * RB) + lkK;
            const uint32_t aKl = Kl0 + j * (8 * RB) + lkK;
#pragma unroll
            for (int cp = 0; cp < 4; cp += 2) {
                uint32_t bh[4], bl[4];
                ldsm_x4(bh, aKh + cp * 32);
                ldsm_x4(bl, aKl + cp * 32);
                mma_bf16(s[j], qh[cp], bh[0], bh[1]);
                mma_bf16(s[j], qh[cp], bl[0], bl[1]);
                mma_bf16(s[j], ql[cp], bh[0], bh[1]);
                mma_bf16(s[j], qh[cp + 1], bh[2], bh[3]);
                mma_bf16(s[j], qh[cp + 1], bl[2], bl[3]);
                mma_bf16(s[j], ql[cp + 1], bh[2], bh[3]);
            }
        }

        const bool diag = (kt == qt);
#pragma unroll
        for (int j = 0; j < 8; j++) {
            const int col = k0 + 8 * j + 2 * t4;
            s[j][0] *= 0.125f; s[j][1] *= 0.125f;
            s[j][2] *= 0.125f; s[j][3] *= 0.125f;
            if (diag) {
                if (col     > r_lo) s[j][0] = -1e30f;
                if (col + 1 > r_lo) s[j][1] = -1e30f;
                if (col     > r_hi) s[j][2] = -1e30f;
                if (col + 1 > r_hi) s[j][3] = -1e30f;
            }
        }

        float mx_lo = -1e30f, mx_hi = -1e30f;
#pragma unroll
        for (int j = 0; j < 8; j++) {
            mx_lo = fmaxf(mx_lo, fmaxf(s[j][0], s[j][1]));
            mx_hi = fmaxf(mx_hi, fmaxf(s[j][2], s[j][3]));
        }
        mx_lo = fmaxf(mx_lo, __shfl_xor_sync(0xFFFFFFFF, mx_lo, 1));
        mx_lo = fmaxf(mx_lo, __shfl_xor_sync(0xFFFFFFFF, mx_lo, 2));
        mx_hi = fmaxf(mx_hi, __shfl_xor_sync(0xFFFFFFFF, mx_hi, 1));
        mx_hi = fmaxf(mx_hi, __shfl_xor_sync(0xFFFFFFFF, mx_hi, 2));

        const float mn_lo = fmaxf(m_lo, mx_lo);
        const float mn_hi = fmaxf(m_hi, mx_hi);
        const float cr_lo = __expf(m_lo - mn_lo);
        const float cr_hi = __expf(m_hi - mn_hi);
        m_lo = mn_lo; m_hi = mn_hi;
        l_lo *= cr_lo; l_hi *= cr_hi;
#pragma unroll
        for (int j = 0; j < 8; j++) {
            o[j][0] *= cr_lo; o[j][1] *= cr_lo;
            o[j][2] *= cr_hi; o[j][3] *= cr_hi;
        }

        uint32_t pah[4][4], pal[4][4];
#pragma unroll
        for (int j = 0; j < 8; j++) {
            float p0 = __expf(s[j][0] - m_lo);
            float p1 = __expf(s[j][1] - m_lo);
            float p2 = __expf(s[j][2] - m_hi);
            float p3 = __expf(s[j][3] - m_hi);
            l_lo += p0 + p1;
            l_hi += p2 + p3;
            uint32_t h01, l01, h23, l23;
            split2(p0, p1, h01, l01);
            split2(p2, p3, h23, l23);
            const int c = j >> 1;
            if ((j & 1) == 0) {
                pah[c][0] = h01; pah[c][1] = h23;
                pal[c][0] = l01; pal[c][1] = l23;
            } else {
                pah[c][2] = h01; pah[c][3] = h23;
                pal[c][2] = l01; pal[c][3] = l23;
            }
        }

#pragma unroll
        for (int j = 0; j < 8; j++) {
            const uint32_t aVh = Vh0 + lkV + j * 16;
            const uint32_t aVl = Vl0 + lkV + j * 16;
#pragma unroll
            for (int cp = 0; cp < 4; cp += 2) {
                uint32_t bh[4], bl[4];
                ldsm_x4_t(bh, aVh + cp * (16 * RB));
                ldsm_x4_t(bl, aVl + cp * (16 * RB));
                mma_bf16(o[j], pah[cp], bh[0], bh[1]);
                mma_bf16(o[j], pah[cp], bl[0], bl[1]);
                mma_bf16(o[j], pal[cp], bh[0], bh[1]);
                mma_bf16(o[j], pah[cp + 1], bh[2], bh[3]);
                mma_bf16(o[j], pah[cp + 1], bl[2], bl[3]);
                mma_bf16(o[j], pal[cp + 1], bh[2], bh[3]);
            }
        }
    }

    l_lo += __shfl_xor_sync(0xFFFFFFFF, l_lo, 1);
    l_lo += __shfl_xor_sync(0xFFFFFFFF, l_lo, 2);
    l_hi += __shfl_xor_sync(0xFFFFFFFF, l_hi, 1);
    l_hi += __shfl_xor_sync(0xFFFFFFFF, l_hi, 2);
    const float inv_lo = 1.0f / l_lo;
    const float inv_hi = 1.0f / l_hi;

    // CTX epilogue: tf32-rounded, K-PERMUTED layout (input of Wo GEMM).
#pragma unroll
    for (int j = 0; j < 8; j++) {
        const int col = hoff + 8 * j + 2 * t4;
        const int kk  = col & 15;
        const int jp  = ((kk & 3) << 2) | (kk >> 2);
        const size_t base_lo = (size_t)(b * SS + r_lo) * DD + (col & ~15);
        const size_t base_hi = (size_t)(b * SS + r_hi) * DD + (col & ~15);
        CTX[base_lo + jp]     = f2tf32f(o[j][0] * inv_lo);
        CTX[base_lo + jp + 4] = f2tf32f(o[j][1] * inv_lo);
        CTX[base_hi + jp]     = f2tf32f(o[j][2] * inv_hi);
        CTX[base_hi + jp + 4] = f2tf32f(o[j][3] * inv_hi);
    }
}

// ---------------------------------------------------------------------------
// Launch
// ---------------------------------------------------------------------------
extern "C" void kernel_launch(void* const* d_in, const int* in_sizes, int n_in,
                              void* d_out, int out_size)
{
    const float* x  = (const float*)d_in[0];
    const float* Wq = (const float*)d_in[1];
    const float* Wk = (const float*)d_in[2];
    const float* Wv = (const float*)d_in[3];
    const float* Wo = (const float*)d_in[4];
    float* out = (float*)d_out;

    __nv_bfloat16 *qh, *ql, *kh, *kl, *vh, *vl;
    float *Cb, *xr, *wr;
    cudaGetSymbolAddress((void**)&qh, g_qh);
    cudaGetSymbolAddress((void**)&ql, g_ql);
    cudaGetSymbolAddress((void**)&kh, g_kh);
    cudaGetSymbolAddress((void**)&kl, g_kl);
    cudaGetSymbolAddress((void**)&vh, g_vh);
    cudaGetSymbolAddress((void**)&vl, g_vl);
    cudaGetSymbolAddress((void**)&Cb, g_C);
    cudaGetSymbolAddress((void**)&xr, g_xr);
    cudaGetSymbolAddress((void**)&wr, g_wr);

    cudaFuncSetAttribute(gemm_tf32<0>, cudaFuncAttributeMaxDynamicSharedMemorySize, GSMEMB);
    cudaFuncSetAttribute(gemm_tf32<1>, cudaFuncAttributeMaxDynamicSharedMemorySize, GSMEMB);

    const int ntot = NX4 + 4 * NW4;
    cvt_all<<<(ntot + 255) / 256, 256>>>(x, Wq, Wk, Wv, Wo, xr, wr);

    dim3 gq(24, MM / BM);
    gemm_tf32<1><<<gq, 256, GSMEMB>>>(xr, wr, nullptr, qh, ql, kh, kl, vh, vl, MM, DD, DD);

    dim3 ga(SS / 64, HH, BB);    // (32, 16, 4)
    attn_mma<<<ga, 128>>>(qh, ql, kh, kl, vh, vl, Cb);

    dim3 gg(DD / BN, MM / BM);
    gemm_tf32<0><<<gg, 256, GSMEMB>>>(Cb, wr + 3 * (size_t)DD * DD, out,
                                      nullptr, nullptr, nullptr, nullptr, nullptr, nullptr,
                                      MM, DD, DD);
}

// round 15
// speedup vs baseline: 1.0345x; 1.0345x over previous
#include <cuda_runtime.h>
#include <cuda_bf16.h>
#include <cstdint>

// Problem constants
#define BB   4
#define SS   2048
#define DD   1024
#define HH   16
#define DKH  64
#define MM   (BB*SS)   // 8192 rows

// bf16 hi/lo scratch for Q,K,V ; fp32 context (K-permuted); tf32-rounded
// K-permuted copies of x, W. Permutation within each 16-k block:
//   j = 4*(k%4) + k/4
__device__ __align__(16) __nv_bfloat16 g_qh[(size_t)MM*DD];
__device__ __align__(16) __nv_bfloat16 g_ql[(size_t)MM*DD];
__device__ __align__(16) __nv_bfloat16 g_kh[(size_t)MM*DD];
__device__ __align__(16) __nv_bfloat16 g_kl[(size_t)MM*DD];
__device__ __align__(16) __nv_bfloat16 g_vh[(size_t)MM*DD];
__device__ __align__(16) __nv_bfloat16 g_vl[(size_t)MM*DD];
__device__ __align__(16) float g_C[(size_t)MM*DD];
__device__ __align__(16) float g_xr[(size_t)MM*DD];
__device__ __align__(16) float g_wr[4][(size_t)DD*DD];

// ---------------------------------------------------------------------------
// helpers
// ---------------------------------------------------------------------------
__device__ __forceinline__ float f2tf32f(float f) {
    unsigned u;
    asm("cvt.rna.tf32.f32 %0, %1;" : "=r"(u) : "f"(f));
    return __uint_as_float(u);
}
__device__ __forceinline__ void mma_tf32(float c[4], unsigned a0, unsigned a1,
                                         unsigned a2, unsigned a3,
                                         unsigned b0, unsigned b1) {
    asm volatile(
        "mma.sync.aligned.m16n8k8.row.col.f32.tf32.tf32.f32 "
        "{%0,%1,%2,%3}, {%4,%5,%6,%7}, {%8,%9}, {%0,%1,%2,%3};\n"
        : "+f"(c[0]), "+f"(c[1]), "+f"(c[2]), "+f"(c[3])
        : "r"(a0), "r"(a1), "r"(a2), "r"(a3), "r"(b0), "r"(b1));
}
__device__ __forceinline__ void mma_bf16(float c[4], const uint32_t a[4],
                                         uint32_t b0, uint32_t b1) {
    asm volatile(
        "mma.sync.aligned.m16n8k16.row.col.f32.bf16.bf16.f32 "
        "{%0,%1,%2,%3}, {%4,%5,%6,%7}, {%8,%9}, {%0,%1,%2,%3};\n"
        : "+f"(c[0]), "+f"(c[1]), "+f"(c[2]), "+f"(c[3])
        : "r"(a[0]), "r"(a[1]), "r"(a[2]), "r"(a[3]), "r"(b0), "r"(b1));
}
__device__ __forceinline__ uint32_t pkbf(float x, float y) {
    __nv_bfloat162 t = __floats2bfloat162_rn(x, y);
    return *reinterpret_cast<uint32_t*>(&t);
}
__device__ __forceinline__ void split2(float x, float y, uint32_t& hi, uint32_t& lo) {
    __nv_bfloat16 hx = __float2bfloat16(x), hy = __float2bfloat16(y);
    hi = (uint32_t)__bfloat16_as_ushort(hx) | ((uint32_t)__bfloat16_as_ushort(hy) << 16);
    lo = pkbf(x - __bfloat162float(hx), y - __bfloat162float(hy));
}
__device__ __forceinline__ uint32_t smem_u32(const void* p) {
    uint32_t a;
    asm("{ .reg .u64 t; cvta.to.shared.u64 t, %1; cvt.u32.u64 %0, t; }" : "=r"(a) : "l"(p));
    return a;
}
__device__ __forceinline__ void ldsm_x4(uint32_t r[4], uint32_t addr) {
    asm volatile("ldmatrix.sync.aligned.m8n8.x4.shared.b16 {%0,%1,%2,%3}, [%4];"
                 : "=r"(r[0]), "=r"(r[1]), "=r"(r[2]), "=r"(r[3]) : "r"(addr));
}
__device__ __forceinline__ void ldsm_x4_t(uint32_t r[4], uint32_t addr) {
    asm volatile("ldmatrix.sync.aligned.m8n8.x4.trans.shared.b16 {%0,%1,%2,%3}, [%4];"
                 : "=r"(r[0]), "=r"(r[1]), "=r"(r[2]), "=r"(r[3]) : "r"(addr));
}
__device__ __forceinline__ void cpa16(uint32_t dst, const void* src) {
    asm volatile("cp.async.cg.shared.global [%0], [%1], 16;" :: "r"(dst), "l"(src));
}

// ---------------------------------------------------------------------------
// Fused fp32 -> tf32-rounded, K-permuted pre-pass for x + 4 weights (1 launch)
// ---------------------------------------------------------------------------
#define NX4 (MM*DD/4)
#define NW4 (DD*DD/4)

__global__ void cvt_all(const float* __restrict__ x,
                        const float* __restrict__ wq, const float* __restrict__ wk,
                        const float* __restrict__ wv, const float* __restrict__ wo,
                        float* __restrict__ xr, float* __restrict__ wr)
{
    int i = blockIdx.x * blockDim.x + threadIdx.x;
    const float* src;
    float* dst;
    size_t li;
    if (i < NX4) {
        src = x; dst = xr; li = (size_t)i * 4;
    } else {
        int j = i - NX4;
        if (j >= 4 * NW4) return;
        const int wsel = j >> 18;             // NW4 = 2^18
        const int r    = j & (NW4 - 1);
        src = (wsel == 0) ? wq : (wsel == 1) ? wk : (wsel == 2) ? wv : wo;
        dst = wr + (size_t)wsel * DD * DD;
        li  = (size_t)r * 4;
    }
    float4 v = *(const float4*)&src[li];
    const int k0 = (int)(li & (DD - 1));
    const int c  = (k0 & 15) >> 2;
    float* d = dst + (li - (k0 & 15)) + c;
    d[0]  = f2tf32f(v.x);
    d[4]  = f2tf32f(v.y);
    d[8]  = f2tf32f(v.z);
    d[12] = f2tf32f(v.w);
}

// ---------------------------------------------------------------------------
// TF32 tensor-core GEMM (round-12, frozen): cp.async 5-stage, 1 barrier/iter,
// K-permuted operands. MODE 0: single W, fp32 out. MODE 1: fused QKV.
// ---------------------------------------------------------------------------
#define BM   128
#define BN   128
#define BKG  16
#define NSTG 5
#define ASTGF (BM*16)
#define BSTGF (BN*16)
#define GSMEMB (NSTG*(ASTGF+BSTGF)*4)   // 81920

#define U(x) __float_as_uint(x)

template<int MODE>
__global__ __launch_bounds__(256, 2)
void gemm_tf32(const float* __restrict__ A, const float* __restrict__ Wbase,
               float* __restrict__ C,
               __nv_bfloat16* __restrict__ Qh, __nv_bfloat16* __restrict__ Ql,
               __nv_bfloat16* __restrict__ Kh, __nv_bfloat16* __restrict__ Kl,
               __nv_bfloat16* __restrict__ Vh, __nv_bfloat16* __restrict__ Vl,
               int M, int N, int K)
{
    extern __shared__ __align__(16) float smf[];
    float (*As)[BM][16] = (float (*)[BM][16])smf;
    float (*Bs)[BN][16] = (float (*)[BN][16])(smf + NSTG * ASTGF);

    const int t    = threadIdx.x;
    const int lane = t & 31;
    const int wid  = t >> 5;
    const int wm   = (wid & 1) * 64;
    const int wn   = (wid >> 1) * 32;
    const int row0 = blockIdx.y * BM;

    int col0;
    const float* W;
    __nv_bfloat16 *Xh = nullptr, *Xl = nullptr;
    if (MODE == 1) {
        const int mat = blockIdx.x >> 3;
        col0 = (blockIdx.x & 7) * BN;
        W    = Wbase + (size_t)mat * DD * DD;
        Xh   = (mat == 0) ? Qh : (mat == 1) ? Kh : Vh;
        Xl   = (mat == 0) ? Ql : (mat == 1) ? Kl : Vl;
    } else {
        col0 = blockIdx.x * BN;
        W    = Wbase;
    }

    const int lm  = t >> 2;
    const int lkv = (t & 3) << 2;

    const float* Arow0 = &A[(size_t)(row0 + lm) * K + lkv];
    const float* Arow1 = &A[(size_t)(row0 + lm + 64) * K + lkv];
    const float* Wrow0 = &W[(size_t)(col0 + lm) * K + lkv];
    const float* Wrow1 = &W[(size_t)(col0 + lm + 64) * K + lkv];

    const uint32_t sA0 = smem_u32(&As[0][lm][lkv]);
    const uint32_t sA1 = smem_u32(&As[0][lm + 64][lkv]);
    const uint32_t sB0 = smem_u32(&Bs[0][lm][lkv]);
    const uint32_t sB1 = smem_u32(&Bs[0][lm + 64][lkv]);

    float acc[4][4][4];
#pragma unroll
    for (int i = 0; i < 4; i++)
#pragma unroll
        for (int j = 0; j < 4; j++)
#pragma unroll
            for (int r = 0; r < 4; r++) acc[i][j][r] = 0.0f;

    const int lq = lane & 3;
    const int lg = lane >> 2;
    const int iters = K / BKG;   // 64

    // prologue: issue stages 0..3 (4 tiles in flight)
#pragma unroll
    for (int i = 0; i < 4; i++) {
        const int k0 = i * BKG;
        const uint32_t ao = i * (ASTGF * 4), bo = i * (BSTGF * 4);
        cpa16(sA0 + ao, Arow0 + k0);
        cpa16(sA1 + ao, Arow1 + k0);
        cpa16(sB0 + bo, Wrow0 + k0);
        cpa16(sB1 + bo, Wrow1 + k0);
        asm volatile("cp.async.commit_group;");
    }

    int st_w = 4;   // next stage to write (mod NSTG)
    for (int i = 0; i < iters; i++) {
        asm volatile("cp.async.wait_group 3;");
        __syncthreads();   // single barrier per iter: guards stage st_w reuse

        if (i + 4 < iters) {
            const int k0 = (i + 4) * BKG;
            const uint32_t ao = st_w * (ASTGF * 4), bo = st_w * (BSTGF * 4);
            cpa16(sA0 + ao, Arow0 + k0);
            cpa16(sA1 + ao, Arow1 + k0);
            cpa16(sB0 + bo, Wrow0 + k0);
            cpa16(sB1 + bo, Wrow1 + k0);
        }
        asm volatile("cp.async.commit_group;");
        if (++st_w == NSTG) st_w = 0;

        const int s = i % NSTG;
        float4 fb[4];
#pragma unroll
        for (int ni = 0; ni < 4; ni++)
            fb[ni] = *(const float4*)&Bs[s][wn + ni * 8 + lg][4 * lq];
#pragma unroll
        for (int mi = 0; mi < 4; mi++) {
            const int mb = wm + mi * 16 + lg;
            const float4 lo = *(const float4*)&As[s][mb][4 * lq];
            const float4 hi = *(const float4*)&As[s][mb + 8][4 * lq];
#pragma unroll
            for (int ni = 0; ni < 4; ni++) {
                mma_tf32(acc[mi][ni], U(lo.x), U(hi.x), U(lo.y), U(hi.y),
                         U(fb[ni].x), U(fb[ni].y));
                mma_tf32(acc[mi][ni], U(lo.z), U(hi.z), U(lo.w), U(hi.w),
                         U(fb[ni].z), U(fb[ni].w));
            }
        }
    }

#pragma unroll
    for (int mi = 0; mi < 4; mi++) {
        const int r0 = row0 + wm + mi * 16 + lg;
#pragma unroll
        for (int ni = 0; ni < 4; ni++) {
            const int c0 = col0 + wn + ni * 8 + lq * 2;
            if (MODE == 1) {
                uint32_t h0, l0, h1, l1;
                split2(acc[mi][ni][0], acc[mi][ni][1], h0, l0);
                split2(acc[mi][ni][2], acc[mi][ni][3], h1, l1);
                *(uint32_t*)&Xh[(size_t)r0 * DD + c0]       = h0;
                *(uint32_t*)&Xl[(size_t)r0 * DD + c0]       = l0;
                *(uint32_t*)&Xh[(size_t)(r0 + 8) * DD + c0] = h1;
                *(uint32_t*)&Xl[(size_t)(r0 + 8) * DD + c0] = l1;
            } else {
                *(float2*)&C[(size_t)r0 * N + c0]       = make_float2(acc[mi][ni][0], acc[mi][ni][1]);
                *(float2*)&C[(size_t)(r0 + 8) * N + c0] = make_float2(acc[mi][ni][2], acc[mi][ni][3]);
            }
        }
    }
}

// ---------------------------------------------------------------------------
// Causal flash attention — round-12 body (frozen), K-permuted CTX epilogue.
// ---------------------------------------------------------------------------
#define KP   72
#define TSH  (64*KP)
#define RB   144
#define TSB  (64*RB)

__global__ __launch_bounds__(128, 3)
void attn_mma(const __nv_bfloat16* __restrict__ Qhg, const __nv_bfloat16* __restrict__ Qlg,
              const __nv_bfloat16* __restrict__ Khg, const __nv_bfloat16* __restrict__ Klg,
              const __nv_bfloat16* __restrict__ Vhg, const __nv_bfloat16* __restrict__ Vlg,
              float* __restrict__ CTX)
{
    __shared__ __align__(16) unsigned short sm[4 * TSH];

    const int tid  = threadIdx.x;
    const int lane = tid & 31;
    const int w    = tid >> 5;
    const int g    = lane >> 2;
    const int t4   = lane & 3;
    const int qt   = (int)gridDim.x - 1 - (int)blockIdx.x;
    const int h    = blockIdx.y;
    const int b    = blockIdx.z;
    const int r_lo = qt * 64 + w * 16 + g;
    const int r_hi = r_lo + 8;
    const int hoff = h * DKH;

    const uint32_t sb  = smem_u32(sm);
    const uint32_t Kh0 = sb, Kl0 = sb + TSB, Vh0 = sb + 2 * TSB, Vl0 = sb + 3 * TSB;
    const uint32_t lkK = (uint32_t)((lane & 7) * RB + (lane >> 3) * 16);
    const uint32_t lkV = (uint32_t)(lane * RB);

    uint32_t qh[4][4], ql[4][4];
#pragma unroll
    for (int c = 0; c < 4; c++) {
        const size_t plo = (size_t)(b * SS + r_lo) * DD + hoff + c * 16 + 2 * t4;
        const size_t phi = (size_t)(b * SS + r_hi) * DD + hoff + c * 16 + 2 * t4;
        qh[c][0] = *(const uint32_t*)&Qhg[plo];
        qh[c][1] = *(const uint32_t*)&Qhg[phi];
        qh[c][2] = *(const uint32_t*)&Qhg[plo + 8];
        qh[c][3] = *(const uint32_t*)&Qhg[phi + 8];
        ql[c][0] = *(const uint32_t*)&Qlg[plo];
        ql[c][1] = *(const uint32_t*)&Qlg[phi];
        ql[c][2] = *(const uint32_t*)&Qlg[plo + 8];
        ql[c][3] = *(const uint32_t*)&Qlg[phi + 8];
    }

    float o[8][4];
#pragma unroll
    for (int j = 0; j < 8; j++)
#pragma unroll
        for (int e = 0; e < 4; e++) o[j][e] = 0.0f;
    float m_lo = -1e30f, m_hi = -1e30f;
    float l_lo = 0.0f,  l_hi = 0.0f;

    for (int kt = 0; kt <= qt; kt++) {
        const int k0 = kt * 64;
        __syncthreads();
        {
            const size_t gbase = (size_t)(b * SS + k0) * DD + hoff;
#pragma unroll
            for (int i = 0; i < 4; i++) {
                int idx = tid + i * 128;
                int r   = idx >> 3;
                int c8  = (idx & 7) << 3;
                size_t go = gbase + (size_t)r * DD + c8;
                int so = r * KP + c8;
                *(uint4*)&sm[0 * TSH + so] = *(const uint4*)&Khg[go];
                *(uint4*)&sm[1 * TSH + so] = *(const uint4*)&Klg[go];
                *(uint4*)&sm[2 * TSH + so] = *(const uint4*)&Vhg[go];
                *(uint4*)&sm[3 * TSH + so] = *(const uint4*)&Vlg[go];
            }
        }
        __syncthreads();

        float s[8][4];
#pragma unroll
        for (int j = 0; j < 8; j++) {
            s[j][0] = s[j][1] = s[j][2] = s[j][3] = 0.0f;
            const uint32_t aKh = Kh0 + j * (8 * RB) + lkK;
            const uint32_t aKl = Kl0 + j * (8 * RB) + lkK;
#pragma unroll
            for (int cp = 0; cp < 4; cp += 2) {
                uint32_t bh[4], bl[4];
                ldsm_x4(bh, aKh + cp * 32);
                ldsm_x4(bl, aKl + cp * 32);
                mma_bf16(s[j], qh[cp], bh[0], bh[1]);
                mma_bf16(s[j], qh[cp], bl[0], bl[1]);
                mma_bf16(s[j], ql[cp], bh[0], bh[1]);
                mma_bf16(s[j], qh[cp + 1], bh[2], bh[3]);
                mma_bf16(s[j], qh[cp + 1], bl[2], bl[3]);
                mma_bf16(s[j], ql[cp + 1], bh[2], bh[3]);
            }
        }

        const bool diag = (kt == qt);
#pragma unroll
        for (int j = 0; j < 8; j++) {
            const int col = k0 + 8 * j + 2 * t4;
            s[j][0] *= 0.125f; s[j][1] *= 0.125f;
            s[j][2] *= 0.125f; s[j][3] *= 0.125f;
            if (diag) {
                if (col     > r_lo) s[j][0] = -1e30f;
                if (col + 1 > r_lo) s[j][1] = -1e30f;
                if (col     > r_hi) s[j][2] = -1e30f;
                if (col + 1 > r_hi) s[j][3] = -1e30f;
            }
        }

        float mx_lo = -1e30f, mx_hi = -1e30f;
#pragma unroll
        for (int j = 0; j < 8; j++) {
            mx_lo = fmaxf(mx_lo, fmaxf(s[j][0], s[j][1]));
            mx_hi = fmaxf(mx_hi, fmaxf(s[j][2], s[j][3]));
        }
        mx_lo = fmaxf(mx_lo, __shfl_xor_sync(0xFFFFFFFF, mx_lo, 1));
        mx_lo = fmaxf(mx_lo, __shfl_xor_sync(0xFFFFFFFF, mx_lo, 2));
        mx_hi = fmaxf(mx_hi, __shfl_xor_sync(0xFFFFFFFF, mx_hi, 1));
        mx_hi = fmaxf(mx_hi, __shfl_xor_sync(0xFFFFFFFF, mx_hi, 2));

        const float mn_lo = fmaxf(m_lo, mx_lo);
        const float mn_hi = fmaxf(m_hi, mx_hi);
        const float cr_lo = __expf(m_lo - mn_lo);
        const float cr_hi = __expf(m_hi - mn_hi);
        m_lo = mn_lo; m_hi = mn_hi;
        l_lo *= cr_lo; l_hi *= cr_hi;
#pragma unroll
        for (int j = 0; j < 8; j++) {
            o[j][0] *= cr_lo; o[j][1] *= cr_lo;
            o[j][2] *= cr_hi; o[j][3] *= cr_hi;
        }

        uint32_t pah[4][4], pal[4][4];
#pragma unroll
        for (int j = 0; j < 8; j++) {
            float p0 = __expf(s[j][0] - m_lo);
            float p1 = __expf(s[j][1] - m_lo);
            float p2 = __expf(s[j][2] - m_hi);
            float p3 = __expf(s[j][3] - m_hi);
            l_lo += p0 + p1;
            l_hi += p2 + p3;
            uint32_t h01, l01, h23, l23;
            split2(p0, p1, h01, l01);
            split2(p2, p3, h23, l23);
            const int c = j >> 1;
            if ((j & 1) == 0) {
                pah[c][0] = h01; pah[c][1] = h23;
                pal[c][0] = l01; pal[c][1] = l23;
            } else {
                pah[c][2] = h01; pah[c][3] = h23;
                pal[c][2] = l01; pal[c][3] = l23;
            }
        }

#pragma unroll
        for (int j = 0; j < 8; j++) {
            const uint32_t aVh = Vh0 + lkV + j * 16;
            const uint32_t aVl = Vl0 + lkV + j * 16;
#pragma unroll
            for (int cp = 0; cp < 4; cp += 2) {
                uint32_t bh[4], bl[4];
                ldsm_x4_t(bh, aVh + cp * (16 * RB));
                ldsm_x4_t(bl, aVl + cp * (16 * RB));
                mma_bf16(o[j], pah[cp], bh[0], bh[1]);
                mma_bf16(o[j], pah[cp], bl[0], bl[1]);
                mma_bf16(o[j], pal[cp], bh[0], bh[1]);
                mma_bf16(o[j], pah[cp + 1], bh[2], bh[3]);
                mma_bf16(o[j], pah[cp + 1], bl[2], bl[3]);
                mma_bf16(o[j], pal[cp + 1], bh[2], bh[3]);
            }
        }
    }

    l_lo += __shfl_xor_sync(0xFFFFFFFF, l_lo, 1);
    l_lo += __shfl_xor_sync(0xFFFFFFFF, l_lo, 2);
    l_hi += __shfl_xor_sync(0xFFFFFFFF, l_hi, 1);
    l_hi += __shfl_xor_sync(0xFFFFFFFF, l_hi, 2);
    const float inv_lo = 1.0f / l_lo;
    const float inv_hi = 1.0f / l_hi;

    // CTX epilogue: tf32-rounded, K-PERMUTED layout (input of Wo GEMM).
#pragma unroll
    for (int j = 0; j < 8; j++) {
        const int col = hoff + 8 * j + 2 * t4;
        const int kk  = col & 15;
        const int jp  = ((kk & 3) << 2) | (kk >> 2);
        const size_t base_lo = (size_t)(b * SS + r_lo) * DD + (col & ~15);
        const size_t base_hi = (size_t)(b * SS + r_hi) * DD + (col & ~15);
        CTX[base_lo + jp]     = f2tf32f(o[j][0] * inv_lo);
        CTX[base_lo + jp + 4] = f2tf32f(o[j][1] * inv_lo);
        CTX[base_hi + jp]     = f2tf32f(o[j][2] * inv_hi);
        CTX[base_hi + jp + 4] = f2tf32f(o[j][3] * inv_hi);
    }
}

// ---------------------------------------------------------------------------
// Launch
// ---------------------------------------------------------------------------
extern "C" void kernel_launch(void* const* d_in, const int* in_sizes, int n_in,
                              void* d_out, int out_size)
{
    const float* x  = (const float*)d_in[0];
    const float* Wq = (const float*)d_in[1];
    const float* Wk = (const float*)d_in[2];
    const float* Wv = (const float*)d_in[3];
    const float* Wo = (const float*)d_in[4];
    float* out = (float*)d_out;

    __nv_bfloat16 *qh, *ql, *kh, *kl, *vh, *vl;
    float *Cb, *xr, *wr;
    cudaGetSymbolAddress((void**)&qh, g_qh);
    cudaGetSymbolAddress((void**)&ql, g_ql);
    cudaGetSymbolAddress((void**)&kh, g_kh);
    cudaGetSymbolAddress((void**)&kl, g_kl);
    cudaGetSymbolAddress((void**)&vh, g_vh);
    cudaGetSymbolAddress((void**)&vl, g_vl);
    cudaGetSymbolAddress((void**)&Cb, g_C);
    cudaGetSymbolAddress((void**)&xr, g_xr);
    cudaGetSymbolAddress((void**)&wr, g_wr);

    cudaFuncSetAttribute(gemm_tf32<0>, cudaFuncAttributeMaxDynamicSharedMemorySize, GSMEMB);
    cudaFuncSetAttribute(gemm_tf32<1>, cudaFuncAttributeMaxDynamicSharedMemorySize, GSMEMB);

    const int ntot = NX4 + 4 * NW4;
    cvt_all<<<(ntot + 255) / 256, 256>>>(x, Wq, Wk, Wv, Wo, xr, wr);

    dim3 gq(24, MM / BM);
    gemm_tf32<1><<<gq, 256, GSMEMB>>>(xr, wr, nullptr, qh, ql, kh, kl, vh, vl, MM, DD, DD);

    dim3 ga(SS / 64, HH, BB);    // (32, 16, 4)
    attn_mma<<<ga, 128>>>(qh, ql, kh, kl, vh, vl, Cb);

    dim3 gg(DD / BN, MM / BM);
    gemm_tf32<0><<<gg, 256, GSMEMB>>>(Cb, wr + 3 * (size_t)DD * DD, out,
                                      nullptr, nullptr, nullptr, nullptr, nullptr, nullptr,
                                      MM, DD, DD);
}